// round 10
// baseline (speedup 1.0000x reference)
#include <cuda_runtime.h>
#include <cuda_bf16.h>

// PLIF neuron scan, T=8. x: [B=32,T=8,S=131072] fp32 -> spikes same shape.
//
// R10: L2-residency play, 256-bit form (ptxas on sm_100a only accepts
// L2::evict hints on .v8.b32/.v4.b64).
//   - stores:  st.global.L2::evict_last.v8.b32  -> output lines sticky in L2;
//     steady-state graph replays overwrite resident dirty lines, no DRAM
//     writeback per replay (output 128MB vs L2 126MB).
//   - loads:   ld.global.nc.L2::evict_first.v8.b32 -> read stream churns in
//     the non-sticky remainder instead of evicting the resident output.
//
// Structure = R8 (validated): one thread = 8 consecutive floats x 8
// timesteps, all 8 loads front-batched (MLP=8 x 32B).

#define VTH 0.5f
#define SPLANE 131072u   // floats per (b,t) plane
#define S8_SHIFT 14
#define S8_MASK 16383

__device__ __forceinline__ void ld256_ef(const float* p, float* v) {
    asm volatile(
        "ld.global.nc.L2::evict_first.v8.b32 {%0,%1,%2,%3,%4,%5,%6,%7}, [%8];"
        : "=f"(v[0]), "=f"(v[1]), "=f"(v[2]), "=f"(v[3]),
          "=f"(v[4]), "=f"(v[5]), "=f"(v[6]), "=f"(v[7])
        : "l"(p));
}

__device__ __forceinline__ void st256_el(float* p, const float* v) {
    asm volatile(
        "st.global.L2::evict_last.v8.b32 [%0], {%1,%2,%3,%4,%5,%6,%7,%8};"
        :: "l"(p),
           "f"(v[0]), "f"(v[1]), "f"(v[2]), "f"(v[3]),
           "f"(v[4]), "f"(v[5]), "f"(v[6]), "f"(v[7])
        : "memory");
}

__global__ __launch_bounds__(256) void plif_kernel(
    const float* __restrict__ x,
    const float* __restrict__ w,
    float* __restrict__ out)
{
    unsigned i = blockIdx.x * 256u + threadIdx.x;   // 0..524287 exact
    unsigned b = i >> S8_SHIFT;
    unsigned s8 = i & S8_MASK;

    float wv = __ldg(w);
    float tau = 1.0f / (1.0f + __expf(-wv));

    unsigned base = (b << 3) * SPLANE + (s8 << 3);  // float offset of (b,0,site)
    const float* px = x + base;
    float* po = out + base;

    // Front-batch all 8 timestep loads (independent of the scan).
    float xv[8][8];
#pragma unroll
    for (int t = 0; t < 8; t++) {
        ld256_ef(px + t * SPLANE, xv[t]);
    }

    // Sequential membrane scan over 8 lanes; store each timestep immediately.
    float m[8];
#pragma unroll
    for (int l = 0; l < 8; l++) m[l] = 0.0f;

#pragma unroll
    for (int t = 0; t < 8; t++) {
        float r[8];
#pragma unroll
        for (int l = 0; l < 8; l++) {
            m[l] = fmaf(tau, m[l], xv[t][l]);
            r[l] = (m[l] > VTH) ? 1.0f : 0.0f;
            m[l] = (m[l] > VTH) ? 0.0f : m[l];
        }
        st256_el(po + t * SPLANE, r);
    }
}

extern "C" void kernel_launch(void* const* d_in, const int* in_sizes, int n_in,
                              void* d_out, int out_size) {
    const float* x = (const float*)d_in[0];
    const float* w = (const float*)d_in[1];
    float* o = (float*)d_out;

    // 524,288 float8 sites -> exact 2048 x 256 grid
    plif_kernel<<<2048, 256>>>(x, w, o);
}

// round 11
// speedup vs baseline: 1.0014x; 1.0014x over previous
#include <cuda_runtime.h>
#include <cuda_bf16.h>

// PLIF neuron scan, T=8. x: [B=32,T=8,S=131072] fp32 -> spikes same shape.
//
// R11: PARTIAL L2-sticky output. R10's full-output evict_last (128MB) exceeds
// L2 (126MB) -> self-thrashing is indistinguishable from ignored hints.
// Discriminator: sticky only batches b<22 (176 planes x 512KB = 88MB << L2),
// leaving ~38MB for read churn + non-sticky writes. If hints are honored,
// steady-state graph replays overwrite resident dirty lines for 88MB of the
// output -> per-replay DRAM ~256MB -> ~170MB.
//
// Loads: evict_first (read stream churns without displacing the sticky set).
// Structure: one thread = 8 consecutive floats x 8 timesteps, loads
// front-batched. Sticky branch is block-uniform (b is constant per block).

#define VTH 0.5f
#define SPLANE 131072u   // floats per (b,t) plane
#define S8_SHIFT 14
#define S8_MASK 16383
#define B_STICKY 22u     // batches with sticky output: 22*8 planes = 88MB

__device__ __forceinline__ void ld256_ef(const float* p, float* v) {
    asm volatile(
        "ld.global.nc.L2::evict_first.v8.b32 {%0,%1,%2,%3,%4,%5,%6,%7}, [%8];"
        : "=f"(v[0]), "=f"(v[1]), "=f"(v[2]), "=f"(v[3]),
          "=f"(v[4]), "=f"(v[5]), "=f"(v[6]), "=f"(v[7])
        : "l"(p));
}

__device__ __forceinline__ void st256_el(float* p, const float* v) {
    asm volatile(
        "st.global.L2::evict_last.v8.b32 [%0], {%1,%2,%3,%4,%5,%6,%7,%8};"
        :: "l"(p),
           "f"(v[0]), "f"(v[1]), "f"(v[2]), "f"(v[3]),
           "f"(v[4]), "f"(v[5]), "f"(v[6]), "f"(v[7])
        : "memory");
}

__device__ __forceinline__ void st256_ef(float* p, const float* v) {
    asm volatile(
        "st.global.L2::evict_first.v8.b32 [%0], {%1,%2,%3,%4,%5,%6,%7,%8};"
        :: "l"(p),
           "f"(v[0]), "f"(v[1]), "f"(v[2]), "f"(v[3]),
           "f"(v[4]), "f"(v[5]), "f"(v[6]), "f"(v[7])
        : "memory");
}

__global__ __launch_bounds__(256) void plif_kernel(
    const float* __restrict__ x,
    const float* __restrict__ w,
    float* __restrict__ out)
{
    unsigned i = blockIdx.x * 256u + threadIdx.x;   // 0..524287 exact
    unsigned b = i >> S8_SHIFT;
    unsigned s8 = i & S8_MASK;
    bool sticky = (b < B_STICKY);                   // block-uniform

    float wv = __ldg(w);
    float tau = 1.0f / (1.0f + __expf(-wv));

    unsigned base = (b << 3) * SPLANE + (s8 << 3);
    const float* px = x + base;
    float* po = out + base;

    // Front-batch all 8 timestep loads (independent of the scan).
    float xv[8][8];
#pragma unroll
    for (int t = 0; t < 8; t++) {
        ld256_ef(px + t * SPLANE, xv[t]);
    }

    // Sequential membrane scan over 8 lanes; store each timestep immediately.
    float m[8];
#pragma unroll
    for (int l = 0; l < 8; l++) m[l] = 0.0f;

#pragma unroll
    for (int t = 0; t < 8; t++) {
        float r[8];
#pragma unroll
        for (int l = 0; l < 8; l++) {
            m[l] = fmaf(tau, m[l], xv[t][l]);
            r[l] = (m[l] > VTH) ? 1.0f : 0.0f;
            m[l] = (m[l] > VTH) ? 0.0f : m[l];
        }
        if (sticky) st256_el(po + t * SPLANE, r);
        else        st256_ef(po + t * SPLANE, r);
    }
}

extern "C" void kernel_launch(void* const* d_in, const int* in_sizes, int n_in,
                              void* d_out, int out_size) {
    const float* x = (const float*)d_in[0];
    const float* w = (const float*)d_in[1];
    float* o = (float*)d_out;

    // 524,288 float8 sites -> exact 2048 x 256 grid
    plif_kernel<<<2048, 256>>>(x, w, o);
}